// round 15
// baseline (speedup 1.0000x reference)
#include <cuda_runtime.h>
#include <math.h>

// FNetBlock: B=4, L=512, D=64, LAG=32  (2048 rows)
// out[row,d] = b0 + c[row,d] * (c>0 ? A_pos[row] : A_neg[row])
//   c[row,d] = sum_e x[row,e] cos(2*pi*d*e/64)
//   m[row,f] = sum_j mask[row,j] cos(2*pi*f*j/512), f=0..256
//   s = sort(m);  A_pos = sum_k W[k] s[k]      + W[32+k] s[225+k]
//                 A_neg = sum_k W[k] s[256-k]  + W[32+k] s[31-k]
// R13 base (best 12.35us): 2 rows/block, 128 threads, shared packed f32x2
// 4-phase Chebyshev chains, dual register-bitonic sorts.
// R15 cuts: hoisted W/bvec prefetch, float2 fold loads, t64 via pad slot.

typedef unsigned long long u64t;
__device__ __forceinline__ u64t pk2(float lo, float hi) {
    u64t r; asm("mov.b64 %0,{%1,%2};" : "=l"(r) : "f"(lo), "f"(hi)); return r;
}
__device__ __forceinline__ void upk2(float& lo, float& hi, u64t v) {
    asm("mov.b64 {%0,%1},%2;" : "=f"(lo), "=f"(hi) : "l"(v));
}
__device__ __forceinline__ u64t fma2_(u64t a, u64t b, u64t c) {
    u64t d; asm("fma.rn.f32x2 %0,%1,%2,%3;" : "=l"(d) : "l"(a), "l"(b), "l"(c)); return d;
}

__global__ __launch_bounds__(128) void fnet_kernel(
    const float* __restrict__ x,     // [2048, 64]
    const float* __restrict__ mask,  // [2048, 512]
    const float* __restrict__ W,     // [64]
    const float* __restrict__ bvec,  // [1]
    float* __restrict__ out)         // [2048, 64]
{
    __shared__ __align__(16) float  sb[2][512];         // mask rows (u)
    __shared__ __align__(16) float2 foldP[2][2][68];    // [row][parity][a]=(we,wo), signed
    __shared__ __align__(16) float  xs[2][64];          // x rows, signed per float4
    __shared__ float  slow[2][4][32];
    __shared__ float  shigh[2][4][32];
    __shared__ float  mbuf[2][4][32];
    __shared__ float  sm128[2];
    __shared__ float  sPP[2][2], sPN[2][2];

    const int tid  = threadIdx.x;     // 0..127
    const int lane = tid & 31;
    const int wr   = tid >> 5;        // warp 0..3
    const int row0 = blockIdx.x * 2;

    // ---- prefetch epilogue constants (overlap DRAM latency with row loads) ----
    // merge roles: wr even -> low side (W[k], W[63-k]); wr odd -> high side.
    const float wMa = __ldg(&W[(wr & 1) ? 32 + lane : lane]);
    const float wMb = __ldg(&W[(wr & 1) ? 31 - lane : 63 - lane]);
    const float b0  = __ldg(&bvec[0]);

    // ---- trig early: one cospif; sines/half-angle via exact sqrt identities ----
    const int f = tid;
    const float cphi = cospif((float)f * (1.0f/128.0f));          // cos(phi), phi=2*pi*f/256
    const float sphi = sqrtf(fmaxf(0.0f, 1.0f - cphi * cphi));    // sin(phi) >= 0 on [0,pi)
    const float cpsi = sqrtf(0.5f * (1.0f + cphi));               // cos(psi), psi=phi/2
    const float spsi = sqrtf(fmaxf(0.0f, 0.5f * (1.0f - cphi)));  // sin(psi) >= 0

    // ---- coalesced vectorized loads (2 rows) ----
    {
        const float4* m4 = (const float4*)(mask + row0 * 512);
        ((float4*)sb)[tid]       = m4[tid];
        ((float4*)sb)[tid + 128] = m4[tid + 128];
    }
    if (tid < 32) {
        const float4* x4 = (const float4*)(x + row0 * 64);
        float4 v = x4[tid];
        if (tid & 1) { v.x = -v.x; v.y = -v.y; v.z = -v.z; v.w = -v.w; } // bake (+,+,-,-)
        ((float4*)xs)[tid] = v;
    }
    __syncthreads();

    // ---- double fold per row (float2 loads), chain-phase sign baked in ----
    {
        const int pp = tid >> 6;
        const int a  = tid & 63;
        const float s  = pp ? -1.0f : 1.0f;
        const float sg = (a & 4) ? -1.0f : 1.0f;   // sign for chain step g=a>>1
        #pragma unroll
        for (int rr = 0; rr < 2; rr++) {
            const float2* u2 = (const float2*)sb[rr];   // u2[i] = (u[2i], u[2i+1])
            float we, wo;
            if (a == 0) {
                const float* u = sb[rr];
                we = fmaf(s, u[256], u[0]);
                wo = (u[1] + u[511]) + s * (u[255] + u[257]);
                // stash tail t64 = u[128] + u[384] in pad slot (p=0 only)
                if (pp == 0) foldP[rr][0][64] = make_float2(u[128] + u[384], 0.f);
            } else {
                float2 za = u2[a];                      // u[2a], u[2a+1]
                float2 zr = u2[255 - a];                // _, u[511-2a]
                float2 zs = u2[256 - a];                // u[512-2a], _
                float2 zc = u2[127 - a];                // _, u[255-2a]
                float2 zd = u2[128 - a];                // u[256-2a], _
                float2 ze = u2[128 + a];                // u[256+2a], u[257+2a]
                we = (za.x + zs.x) + s * (zd.x + ze.x);
                wo = (za.y + zr.y) + s * (zc.y + ze.y);
            }
            foldP[rr][pp][a] = make_float2(we * sg, wo * sg);
        }
    }
    __syncthreads();

    // ---- folded DFT for BOTH rows: 4-phase chains, zero negations ----
    const int p = f & 1;
    const float c2 = fmaf(2.0f*cphi, cphi, -1.0f);      // cos(2phi)
    const float s2 = 2.0f * sphi * cphi;                // sin(2phi)
    const float wpe0 = fmaf(cpsi, c2,  spsi * s2);      // cos(psi-2phi)
    const float wo0  = fmaf(cpsi, cphi, -(spsi * sphi));// cos(psi+phi)
    const float wpo0 = fmaf(cpsi, cphi,  (spsi * sphi));// cos(psi-phi)

    const u64t T2  = pk2( 2.0f * c2,  2.0f * c2);
    const u64t NT2 = pk2(-2.0f * c2, -2.0f * c2);
    u64t M0 = pk2(1.0f,  cpsi);   u64t P0 = pk2(-c2,  -wpe0);
    u64t M1 = pk2(cphi,  wo0);    u64t P1 = pk2(-cphi, -wpo0);

    u64t A0a = 0, A1a = 0, A0b = 0, A1b = 0;
    const ulonglong2* wqA = (const ulonglong2*)&foldP[0][p][0];
    const ulonglong2* wqB = (const ulonglong2*)&foldP[1][p][0];
    #pragma unroll
    for (int j = 0; j < 8; ++j) {
        ulonglong2 qa, qb;
        qa = wqA[4*j];     qb = wqB[4*j];       // g = 4j   (+)
        A0a = fma2_(qa.x, M0, A0a);  A1a = fma2_(qa.y, M1, A1a);
        A0b = fma2_(qb.x, M0, A0b);  A1b = fma2_(qb.y, M1, A1b);
        u64t n0 = fma2_(T2, M0, P0), n1 = fma2_(T2, M1, P1);
        qa = wqA[4*j + 1]; qb = wqB[4*j + 1];   // g = 4j+1 (+)
        A0a = fma2_(qa.x, n0, A0a);  A1a = fma2_(qa.y, n1, A1a);
        A0b = fma2_(qb.x, n0, A0b);  A1b = fma2_(qb.y, n1, A1b);
        u64t m0 = fma2_(NT2, n0, M0), m1 = fma2_(NT2, n1, M1);
        qa = wqA[4*j + 2]; qb = wqB[4*j + 2];   // g = 4j+2 (-)
        A0a = fma2_(qa.x, m0, A0a);  A1a = fma2_(qa.y, m1, A1a);
        A0b = fma2_(qb.x, m0, A0b);  A1b = fma2_(qb.y, m1, A1b);
        u64t r0 = fma2_(T2, m0, n0), r1 = fma2_(T2, m1, n1);
        qa = wqA[4*j + 3]; qb = wqB[4*j + 3];   // g = 4j+3 (-)
        A0a = fma2_(qa.x, r0, A0a);  A1a = fma2_(qa.y, r1, A1a);
        A0b = fma2_(qb.x, r0, A0b);  A1b = fma2_(qb.y, r1, A1b);
        M0 = fma2_(NT2, r0, m0);  M1 = fma2_(NT2, r1, m1);
        P0 = r0;  P1 = r1;
    }
    float vA0, vA1, vB0, vB1;
    {
        float Ea, Oa, Eb, Ob, e1, o1;
        upk2(Ea, Oa, A0a); upk2(e1, o1, A1a); Ea += e1; Oa += o1;
        upk2(Eb, Ob, A0b); upk2(e1, o1, A1b); Eb += e1; Ob += o1;
        if (p == 0) {                  // tail: t64 * cos(pi*f/2), from pad slot
            float sgn = (f & 2) ? -1.f : 1.f;
            Ea = fmaf(sgn, foldP[0][0][64].x, Ea);
            Eb = fmaf(sgn, foldP[1][0][64].x, Eb);
        }
        vA0 = Ea + Oa;  vA1 = Ea - Oa; // m[f], m[256-f] row A
        vB0 = Eb + Ob;  vB1 = Eb - Ob; // row B
    }

    // ---- m[128] per row: warp3 -> row0, warp2 -> row1 (float4 loads) ----
    if (wr >= 2) {
        int rr = 3 - wr;
        const float4* u4 = (const float4*)sb[rr];   // (u[4b],u[4b+1],u[4b+2],u[4b+3])
        float s = 0.f;
        #pragma unroll
        for (int q = 0; q < 4; q++) {
            float4 v = u4[lane + q * 32];
            s += v.x - v.z;
        }
        #pragma unroll
        for (int o = 16; o; o >>= 1) s += __shfl_xor_sync(0xffffffffu, s, o);
        if (lane == 0) sm128[rr] = s;
    }

    // ---- dual warp bitonic sorts of 64 (interleaved for ILP) ----
    #pragma unroll
    for (int k = 2; k <= 32; k <<= 1) {
        #pragma unroll
        for (int j = k >> 1; j > 0; j >>= 1) {
            bool up0 = ((lane & k) == 0);
            bool up1 = (((lane + 32) & k) == 0);
            float pA0 = __shfl_xor_sync(0xffffffffu, vA0, j);
            float pA1 = __shfl_xor_sync(0xffffffffu, vA1, j);
            float pB0 = __shfl_xor_sync(0xffffffffu, vB0, j);
            float pB1 = __shfl_xor_sync(0xffffffffu, vB1, j);
            bool low = ((lane & j) == 0);
            vA0 = (low == up0) ? fminf(vA0, pA0) : fmaxf(vA0, pA0);
            vA1 = (low == up1) ? fminf(vA1, pA1) : fmaxf(vA1, pA1);
            vB0 = (low == up0) ? fminf(vB0, pB0) : fmaxf(vB0, pB0);
            vB1 = (low == up1) ? fminf(vB1, pB1) : fmaxf(vB1, pB1);
        }
    }
    {   // k = 64 stage: j=32 crosses regs, then clean
        float loA = fminf(vA0, vA1), hiA = fmaxf(vA0, vA1);
        float loB = fminf(vB0, vB1), hiB = fmaxf(vB0, vB1);
        vA0 = loA; vA1 = hiA; vB0 = loB; vB1 = hiB;
        #pragma unroll
        for (int j = 16; j > 0; j >>= 1) {
            float pA0 = __shfl_xor_sync(0xffffffffu, vA0, j);
            float pA1 = __shfl_xor_sync(0xffffffffu, vA1, j);
            float pB0 = __shfl_xor_sync(0xffffffffu, vB0, j);
            float pB1 = __shfl_xor_sync(0xffffffffu, vB1, j);
            bool low = ((lane & j) == 0);
            vA0 = low ? fminf(vA0, pA0) : fmaxf(vA0, pA0);
            vA1 = low ? fminf(vA1, pA1) : fmaxf(vA1, pA1);
            vB0 = low ? fminf(vB0, pB0) : fmaxf(vB0, pB0);
            vB1 = low ? fminf(vB1, pB1) : fmaxf(vB1, pB1);
        }
    }
    slow [0][wr][lane] = vA0;   shigh[0][wr][lane] = vA1;
    slow [1][wr][lane] = vB0;   shigh[1][wr][lane] = vB1;
    __syncthreads();

    // ---- level-1 merges (keep 32 extremes of 64), both rows per warp ----
    #pragma unroll
    for (int rr = 0; rr < 2; rr++) {
        float res;
        if      (wr == 0) res = fminf(slow [rr][0][lane], slow [rr][1][31-lane]);
        else if (wr == 1) res = fminf(slow [rr][2][lane], slow [rr][3][31-lane]);
        else if (wr == 2) res = fmaxf(shigh[rr][0][lane], shigh[rr][1][31-lane]);
        else              res = fmaxf(shigh[rr][2][lane], shigh[rr][3][31-lane]);
        #pragma unroll
        for (int j = 16; j > 0; j >>= 1) {   // bitonic clean -> ascending
            float pv = __shfl_xor_sync(0xffffffffu, res, j);
            res = ((lane & j) == 0) ? fminf(res, pv) : fmaxf(res, pv);
        }
        mbuf[rr][wr][lane] = res;
    }
    __syncthreads();

    // ---- final merges + m128 insert + epilogue dots (one task per warp) ----
    {
        int rr = wr >> 1;
        if ((wr & 1) == 0) {      // low side of row rr
            float lowv = fminf(mbuf[rr][0][lane], mbuf[rr][1][31-lane]);
            #pragma unroll
            for (int j = 16; j > 0; j >>= 1) {
                float pv = __shfl_xor_sync(0xffffffffu, lowv, j);
                lowv = ((lane & j) == 0) ? fminf(lowv, pv) : fmaxf(lowv, pv);
            }
            float m128 = sm128[rr];
            unsigned bal = __ballot_sync(0xffffffffu, lowv < m128);
            int cnt = __popc(bal);
            float sh = __shfl_up_sync(0xffffffffu, lowv, 1);
            if (lane >= cnt) lowv = (lane == cnt) ? m128 : sh;
            float pp = wMa * lowv;             // W[lane]
            float pn = wMb * lowv;             // W[63-lane]
            #pragma unroll
            for (int o = 16; o; o >>= 1) {
                pp += __shfl_xor_sync(0xffffffffu, pp, o);
                pn += __shfl_xor_sync(0xffffffffu, pn, o);
            }
            if (lane == 0) { sPP[rr][0] = pp; sPN[rr][0] = pn; }
        } else {                  // high side of row rr
            float highv = fmaxf(mbuf[rr][2][lane], mbuf[rr][3][31-lane]);
            #pragma unroll
            for (int j = 16; j > 0; j >>= 1) {
                float pv = __shfl_xor_sync(0xffffffffu, highv, j);
                highv = ((lane & j) == 0) ? fminf(highv, pv) : fmaxf(highv, pv);
            }
            float m128 = sm128[rr];
            unsigned bal = __ballot_sync(0xffffffffu, highv < m128);
            int cnt = __popc(bal);
            float shd = __shfl_down_sync(0xffffffffu, highv, 1);
            highv = (lane + 1 < cnt) ? shd : ((lane + 1 == cnt) ? m128 : highv);
            float pp = wMa * highv;            // W[32+lane]
            float pn = wMb * highv;            // W[31-lane]
            #pragma unroll
            for (int o = 16; o; o >>= 1) {
                pp += __shfl_xor_sync(0xffffffffu, pp, o);
                pn += __shfl_xor_sync(0xffffffffu, pn, o);
            }
            if (lane == 0) { sPP[rr][1] = pp; sPN[rr][1] = pn; }
        }
    }

    // ---- x-transform, packed 4-phase chains: thread -> (row tid>>6, d tid&63) ----
    float cval;
    {
        int rr = tid >> 6;
        int d  = tid & 63;
        float cth = cospif((float)d * (1.0f/32.0f));     // cos(theta), theta = 2*pi*d/64
        float c2t = fmaf(2.0f*cth, cth, -1.0f);          // cos(2theta)
        const u64t Tx  = pk2( 2.0f*c2t,  2.0f*c2t);
        const u64t NTx = pk2(-2.0f*c2t, -2.0f*c2t);
        u64t M  = pk2(1.0f, cth);                        // (cos(2h t), cos((2h+1)t))
        u64t P  = pk2(-c2t, -cth);
        u64t acc = 0;
        const u64t* xrp = (const u64t*)xs[rr];           // signed (x[2h], x[2h+1])
        #pragma unroll
        for (int j = 0; j < 8; ++j) {
            acc = fma2_(xrp[4*j],     M, acc);
            u64t n = fma2_(Tx, M, P);
            acc = fma2_(xrp[4*j + 1], n, acc);
            u64t m = fma2_(NTx, n, M);
            acc = fma2_(xrp[4*j + 2], m, acc);
            u64t r = fma2_(Tx, m, n);
            acc = fma2_(xrp[4*j + 3], r, acc);
            M = fma2_(NTx, r, m);  P = r;
        }
        float ca, cb;
        upk2(ca, cb, acc);
        cval = ca + cb;
    }
    __syncthreads();

    // ---- output: 128 threads -> 128 outputs, coalesced ----
    {
        int rr = tid >> 6;
        int d  = tid & 63;
        float Ap = sPP[rr][0] + sPP[rr][1];
        float An = sPN[rr][0] + sPN[rr][1];
        float A = (cval > 0.f) ? Ap : An;
        out[(row0 + rr) * 64 + d] = fmaf(cval, A, b0);
    }
}

extern "C" void kernel_launch(void* const* d_in, const int* in_sizes, int n_in,
                              void* d_out, int out_size) {
    const float* x    = (const float*)d_in[0];
    const float* mask = (const float*)d_in[1];
    const float* W    = (const float*)d_in[2];
    const float* b    = (const float*)d_in[3];
    fnet_kernel<<<1024, 128>>>(x, mask, W, b, (float*)d_out);
}

// round 16
// speedup vs baseline: 1.0495x; 1.0495x over previous
#include <cuda_runtime.h>
#include <math.h>

// FNetBlock: B=4, L=512, D=64, LAG=32  (2048 rows)
// out[row,d] = b0 + c[row,d] * (c>0 ? A_pos[row] : A_neg[row])
//   c[row,d] = sum_e x[row,e] cos(2*pi*d*e/64)
//   m[row,f] = sum_j mask[row,j] cos(2*pi*f*j/512), f=0..256
//   s = sort(m);  A_pos = sum_k W[k] s[k]      + W[32+k] s[225+k]
//                 A_neg = sum_k W[k] s[256-k]  + W[32+k] s[31-k]
// R13 base (best 12.35us): 2 rows/block, 128 threads, shared packed f32x2
// 4-phase Chebyshev chains, dual register-bitonic sorts.
// R16: x-transform hoisted BEFORE the sort so its FMA-pipe chain fills the
// shfl-latency gaps of the MIO-bound sort (issue-slot packing, zero added
// instructions); W/bvec prefetched at kernel start.

typedef unsigned long long u64t;
__device__ __forceinline__ u64t pk2(float lo, float hi) {
    u64t r; asm("mov.b64 %0,{%1,%2};" : "=l"(r) : "f"(lo), "f"(hi)); return r;
}
__device__ __forceinline__ void upk2(float& lo, float& hi, u64t v) {
    asm("mov.b64 {%0,%1},%2;" : "=f"(lo), "=f"(hi) : "l"(v));
}
__device__ __forceinline__ u64t fma2_(u64t a, u64t b, u64t c) {
    u64t d; asm("fma.rn.f32x2 %0,%1,%2,%3;" : "=l"(d) : "l"(a), "l"(b), "l"(c)); return d;
}

__global__ __launch_bounds__(128) void fnet_kernel(
    const float* __restrict__ x,     // [2048, 64]
    const float* __restrict__ mask,  // [2048, 512]
    const float* __restrict__ W,     // [64]
    const float* __restrict__ bvec,  // [1]
    float* __restrict__ out)         // [2048, 64]
{
    __shared__ __align__(16) float  sb[2][512];         // mask rows (u)
    __shared__ __align__(16) float2 foldP[2][2][68];    // [row][parity][a]=(we,wo), signed
    __shared__ __align__(16) float  xs[2][64];          // x rows, signed per float4
    __shared__ float  slow[2][4][32];
    __shared__ float  shigh[2][4][32];
    __shared__ float  mbuf[2][4][32];
    __shared__ float  sm128[2];
    __shared__ float  sPP[2][2], sPN[2][2];

    const int tid  = threadIdx.x;     // 0..127
    const int lane = tid & 31;
    const int wr   = tid >> 5;        // warp 0..3
    const int row0 = blockIdx.x * 2;

    // ---- prefetch epilogue constants (hide L2 latency behind row loads) ----
    const float wMa = __ldg(&W[(wr & 1) ? 32 + lane : lane]);
    const float wMb = __ldg(&W[(wr & 1) ? 31 - lane : 63 - lane]);
    const float b0  = __ldg(&bvec[0]);

    // ---- trig early: one cospif; sines/half-angle via exact sqrt identities ----
    const int f = tid;
    const float cphi = cospif((float)f * (1.0f/128.0f));          // cos(phi), phi=2*pi*f/256
    const float sphi = sqrtf(fmaxf(0.0f, 1.0f - cphi * cphi));    // sin(phi) >= 0 on [0,pi)
    const float cpsi = sqrtf(0.5f * (1.0f + cphi));               // cos(psi), psi=phi/2
    const float spsi = sqrtf(fmaxf(0.0f, 0.5f * (1.0f - cphi)));  // sin(psi) >= 0

    // ---- coalesced vectorized loads (2 rows) ----
    {
        const float4* m4 = (const float4*)(mask + row0 * 512);
        ((float4*)sb)[tid]       = m4[tid];
        ((float4*)sb)[tid + 128] = m4[tid + 128];
    }
    if (tid < 32) {
        const float4* x4 = (const float4*)(x + row0 * 64);
        float4 v = x4[tid];
        if (tid & 1) { v.x = -v.x; v.y = -v.y; v.z = -v.z; v.w = -v.w; } // bake (+,+,-,-)
        ((float4*)xs)[tid] = v;
    }
    __syncthreads();

    // ---- double fold per row, with chain-phase sign baked in (R13 form) ----
    {
        const int pp = tid >> 6;
        const int a  = tid & 63;
        const float s  = pp ? -1.0f : 1.0f;
        const float sg = (a & 4) ? -1.0f : 1.0f;   // sign for chain step g=a>>1
        #pragma unroll
        for (int rr = 0; rr < 2; rr++) {
            const float* u = sb[rr];
            float we, wo;
            if (a == 0) {
                we = fmaf(s, u[256], u[0]);
                wo = (u[1] + u[511]) + s * (u[255] + u[257]);
            } else {
                we = (u[2*a] + u[512-2*a]) + s * (u[256-2*a] + u[256+2*a]);
                wo = (u[2*a+1] + u[511-2*a]) + s * (u[255-2*a] + u[257+2*a]);
            }
            foldP[rr][pp][a] = make_float2(we * sg, wo * sg);
        }
    }
    __syncthreads();

    // ---- folded DFT for BOTH rows: 4-phase chains, zero negations ----
    const int p = f & 1;
    const float c2 = fmaf(2.0f*cphi, cphi, -1.0f);      // cos(2phi)
    const float s2 = 2.0f * sphi * cphi;                // sin(2phi)
    const float wpe0 = fmaf(cpsi, c2,  spsi * s2);      // cos(psi-2phi)
    const float wo0  = fmaf(cpsi, cphi, -(spsi * sphi));// cos(psi+phi)
    const float wpo0 = fmaf(cpsi, cphi,  (spsi * sphi));// cos(psi-phi)

    const u64t T2  = pk2( 2.0f * c2,  2.0f * c2);
    const u64t NT2 = pk2(-2.0f * c2, -2.0f * c2);
    u64t M0 = pk2(1.0f,  cpsi);   u64t P0 = pk2(-c2,  -wpe0);
    u64t M1 = pk2(cphi,  wo0);    u64t P1 = pk2(-cphi, -wpo0);

    u64t A0a = 0, A1a = 0, A0b = 0, A1b = 0;
    const ulonglong2* wqA = (const ulonglong2*)&foldP[0][p][0];
    const ulonglong2* wqB = (const ulonglong2*)&foldP[1][p][0];
    #pragma unroll
    for (int j = 0; j < 8; ++j) {
        ulonglong2 qa, qb;
        qa = wqA[4*j];     qb = wqB[4*j];       // g = 4j   (+)
        A0a = fma2_(qa.x, M0, A0a);  A1a = fma2_(qa.y, M1, A1a);
        A0b = fma2_(qb.x, M0, A0b);  A1b = fma2_(qb.y, M1, A1b);
        u64t n0 = fma2_(T2, M0, P0), n1 = fma2_(T2, M1, P1);
        qa = wqA[4*j + 1]; qb = wqB[4*j + 1];   // g = 4j+1 (+)
        A0a = fma2_(qa.x, n0, A0a);  A1a = fma2_(qa.y, n1, A1a);
        A0b = fma2_(qb.x, n0, A0b);  A1b = fma2_(qb.y, n1, A1b);
        u64t m0 = fma2_(NT2, n0, M0), m1 = fma2_(NT2, n1, M1);
        qa = wqA[4*j + 2]; qb = wqB[4*j + 2];   // g = 4j+2 (-)
        A0a = fma2_(qa.x, m0, A0a);  A1a = fma2_(qa.y, m1, A1a);
        A0b = fma2_(qb.x, m0, A0b);  A1b = fma2_(qb.y, m1, A1b);
        u64t r0 = fma2_(T2, m0, n0), r1 = fma2_(T2, m1, n1);
        qa = wqA[4*j + 3]; qb = wqB[4*j + 3];   // g = 4j+3 (-)
        A0a = fma2_(qa.x, r0, A0a);  A1a = fma2_(qa.y, r1, A1a);
        A0b = fma2_(qb.x, r0, A0b);  A1b = fma2_(qb.y, r1, A1b);
        M0 = fma2_(NT2, r0, m0);  M1 = fma2_(NT2, r1, m1);
        P0 = r0;  P1 = r1;
    }
    float vA0, vA1, vB0, vB1;
    {
        float Ea, Oa, Eb, Ob, e1, o1;
        upk2(Ea, Oa, A0a); upk2(e1, o1, A1a); Ea += e1; Oa += o1;
        upk2(Eb, Ob, A0b); upk2(e1, o1, A1b); Eb += e1; Ob += o1;
        if (p == 0) {                  // tail: v_e[64]*cos(pi*f/2)
            float sgn = (f & 2) ? -1.f : 1.f;
            Ea = fmaf(sgn, sb[0][128] + sb[0][384], Ea);
            Eb = fmaf(sgn, sb[1][128] + sb[1][384], Eb);
        }
        vA0 = Ea + Oa;  vA1 = Ea - Oa; // m[f], m[256-f] row A
        vB0 = Eb + Ob;  vB1 = Eb - Ob; // row B
    }

    // ---- m[128] per row: warp3 -> row0, warp2 -> row1 (float4 loads) ----
    if (wr >= 2) {
        int rr = 3 - wr;
        const float4* u4 = (const float4*)sb[rr];   // (u[4b],u[4b+1],u[4b+2],u[4b+3])
        float s = 0.f;
        #pragma unroll
        for (int q = 0; q < 4; q++) {
            float4 v = u4[lane + q * 32];
            s += v.x - v.z;
        }
        #pragma unroll
        for (int o = 16; o; o >>= 1) s += __shfl_xor_sync(0xffffffffu, s, o);
        if (lane == 0) sm128[rr] = s;
    }

    // ==== x-transform HERE (FMA-pipe stream, independent of sort) ====
    // Interleaves with the MIO-bound sort below: fills shfl-latency slots.
    float cval;
    {
        int rr = tid >> 6;
        int d  = tid & 63;
        float cth = cospif((float)d * (1.0f/32.0f));     // cos(theta), theta = 2*pi*d/64
        float c2t = fmaf(2.0f*cth, cth, -1.0f);          // cos(2theta)
        const u64t Tx  = pk2( 2.0f*c2t,  2.0f*c2t);
        const u64t NTx = pk2(-2.0f*c2t, -2.0f*c2t);
        u64t Mx = pk2(1.0f, cth);                        // (cos(2h t), cos((2h+1)t))
        u64t Px = pk2(-c2t, -cth);
        u64t acc = 0;
        const u64t* xrp = (const u64t*)xs[rr];           // signed (x[2h], x[2h+1])
        #pragma unroll
        for (int j = 0; j < 8; ++j) {
            acc = fma2_(xrp[4*j],     Mx, acc);
            u64t n = fma2_(Tx, Mx, Px);
            acc = fma2_(xrp[4*j + 1], n, acc);
            u64t m = fma2_(NTx, n, Mx);
            acc = fma2_(xrp[4*j + 2], m, acc);
            u64t r = fma2_(Tx, m, n);
            acc = fma2_(xrp[4*j + 3], r, acc);
            Mx = fma2_(NTx, r, m);  Px = r;
        }
        float ca, cb;
        upk2(ca, cb, acc);
        cval = ca + cb;
    }

    // ---- dual warp bitonic sorts of 64 (interleaved for ILP) ----
    #pragma unroll
    for (int k = 2; k <= 32; k <<= 1) {
        #pragma unroll
        for (int j = k >> 1; j > 0; j >>= 1) {
            bool up0 = ((lane & k) == 0);
            bool up1 = (((lane + 32) & k) == 0);
            float pA0 = __shfl_xor_sync(0xffffffffu, vA0, j);
            float pA1 = __shfl_xor_sync(0xffffffffu, vA1, j);
            float pB0 = __shfl_xor_sync(0xffffffffu, vB0, j);
            float pB1 = __shfl_xor_sync(0xffffffffu, vB1, j);
            bool low = ((lane & j) == 0);
            vA0 = (low == up0) ? fminf(vA0, pA0) : fmaxf(vA0, pA0);
            vA1 = (low == up1) ? fminf(vA1, pA1) : fmaxf(vA1, pA1);
            vB0 = (low == up0) ? fminf(vB0, pB0) : fmaxf(vB0, pB0);
            vB1 = (low == up1) ? fminf(vB1, pB1) : fmaxf(vB1, pB1);
        }
    }
    {   // k = 64 stage: j=32 crosses regs, then clean
        float loA = fminf(vA0, vA1), hiA = fmaxf(vA0, vA1);
        float loB = fminf(vB0, vB1), hiB = fmaxf(vB0, vB1);
        vA0 = loA; vA1 = hiA; vB0 = loB; vB1 = hiB;
        #pragma unroll
        for (int j = 16; j > 0; j >>= 1) {
            float pA0 = __shfl_xor_sync(0xffffffffu, vA0, j);
            float pA1 = __shfl_xor_sync(0xffffffffu, vA1, j);
            float pB0 = __shfl_xor_sync(0xffffffffu, vB0, j);
            float pB1 = __shfl_xor_sync(0xffffffffu, vB1, j);
            bool low = ((lane & j) == 0);
            vA0 = low ? fminf(vA0, pA0) : fmaxf(vA0, pA0);
            vA1 = low ? fminf(vA1, pA1) : fmaxf(vA1, pA1);
            vB0 = low ? fminf(vB0, pB0) : fmaxf(vB0, pB0);
            vB1 = low ? fminf(vB1, pB1) : fmaxf(vB1, pB1);
        }
    }
    slow [0][wr][lane] = vA0;   shigh[0][wr][lane] = vA1;
    slow [1][wr][lane] = vB0;   shigh[1][wr][lane] = vB1;
    __syncthreads();

    // ---- level-1 merges (keep 32 extremes of 64), both rows per warp ----
    #pragma unroll
    for (int rr = 0; rr < 2; rr++) {
        float res;
        if      (wr == 0) res = fminf(slow [rr][0][lane], slow [rr][1][31-lane]);
        else if (wr == 1) res = fminf(slow [rr][2][lane], slow [rr][3][31-lane]);
        else if (wr == 2) res = fmaxf(shigh[rr][0][lane], shigh[rr][1][31-lane]);
        else              res = fmaxf(shigh[rr][2][lane], shigh[rr][3][31-lane]);
        #pragma unroll
        for (int j = 16; j > 0; j >>= 1) {   // bitonic clean -> ascending
            float pv = __shfl_xor_sync(0xffffffffu, res, j);
            res = ((lane & j) == 0) ? fminf(res, pv) : fmaxf(res, pv);
        }
        mbuf[rr][wr][lane] = res;
    }
    __syncthreads();

    // ---- final merges + m128 insert + epilogue dots (one task per warp) ----
    {
        int rr = wr >> 1;
        if ((wr & 1) == 0) {      // low side of row rr
            float lowv = fminf(mbuf[rr][0][lane], mbuf[rr][1][31-lane]);
            #pragma unroll
            for (int j = 16; j > 0; j >>= 1) {
                float pv = __shfl_xor_sync(0xffffffffu, lowv, j);
                lowv = ((lane & j) == 0) ? fminf(lowv, pv) : fmaxf(lowv, pv);
            }
            float m128 = sm128[rr];
            unsigned bal = __ballot_sync(0xffffffffu, lowv < m128);
            int cnt = __popc(bal);
            float sh = __shfl_up_sync(0xffffffffu, lowv, 1);
            if (lane >= cnt) lowv = (lane == cnt) ? m128 : sh;
            float pp = wMa * lowv;             // W[lane]
            float pn = wMb * lowv;             // W[63-lane]
            #pragma unroll
            for (int o = 16; o; o >>= 1) {
                pp += __shfl_xor_sync(0xffffffffu, pp, o);
                pn += __shfl_xor_sync(0xffffffffu, pn, o);
            }
            if (lane == 0) { sPP[rr][0] = pp; sPN[rr][0] = pn; }
        } else {                  // high side of row rr
            float highv = fmaxf(mbuf[rr][2][lane], mbuf[rr][3][31-lane]);
            #pragma unroll
            for (int j = 16; j > 0; j >>= 1) {
                float pv = __shfl_xor_sync(0xffffffffu, highv, j);
                highv = ((lane & j) == 0) ? fminf(highv, pv) : fmaxf(highv, pv);
            }
            float m128 = sm128[rr];
            unsigned bal = __ballot_sync(0xffffffffu, highv < m128);
            int cnt = __popc(bal);
            float shd = __shfl_down_sync(0xffffffffu, highv, 1);
            highv = (lane + 1 < cnt) ? shd : ((lane + 1 == cnt) ? m128 : highv);
            float pp = wMa * highv;            // W[32+lane]
            float pn = wMb * highv;            // W[31-lane]
            #pragma unroll
            for (int o = 16; o; o >>= 1) {
                pp += __shfl_xor_sync(0xffffffffu, pp, o);
                pn += __shfl_xor_sync(0xffffffffu, pn, o);
            }
            if (lane == 0) { sPP[rr][1] = pp; sPN[rr][1] = pn; }
        }
    }
    __syncthreads();

    // ---- output: 128 threads -> 128 outputs, coalesced ----
    {
        int rr = tid >> 6;
        int d  = tid & 63;
        float Ap = sPP[rr][0] + sPP[rr][1];
        float An = sPN[rr][0] + sPN[rr][1];
        float A = (cval > 0.f) ? Ap : An;
        out[(row0 + rr) * 64 + d] = fmaf(cval, A, b0);
    }
}

extern "C" void kernel_launch(void* const* d_in, const int* in_sizes, int n_in,
                              void* d_out, int out_size) {
    const float* x    = (const float*)d_in[0];
    const float* mask = (const float*)d_in[1];
    const float* W    = (const float*)d_in[2];
    const float* b    = (const float*)d_in[3];
    fnet_kernel<<<1024, 128>>>(x, mask, W, b, (float*)d_out);
}